// round 6
// baseline (speedup 1.0000x reference)
#include <cuda_runtime.h>

#define B_  8
#define N_  512
#define F_  32
#define BN_ (B_ * N_)

// Scratch (allocation-free rule: __device__ globals)
__device__ float g_x1[BN_ * F_];
__device__ float g_inv[BN_];

// ---------------------------------------------------------------------------
// Prep kernel: one warp per (b,n) row.
//  - g_inv[row] = 1 / max(sum_j A[row,j], eps)   (A is 0/1 -> |A| == A)
//  - g_x1 = relu(relu(x@Wn1+bn1)@Wn2+bn2)
//  - outX2 = relu(relu(x@Ws1+bs1)@Ws2+bs2)       (self path; agg adds onto it)
// lane = feature index; input row broadcast via shfl. Weights are L1-resident.
// ---------------------------------------------------------------------------
__global__ __launch_bounds__(256)
void prep_kernel(const float* __restrict__ x, const float* __restrict__ A,
                 const float* __restrict__ Wn1, const float* __restrict__ bn1,
                 const float* __restrict__ Wn2, const float* __restrict__ bn2,
                 const float* __restrict__ Ws1, const float* __restrict__ bs1,
                 const float* __restrict__ Ws2, const float* __restrict__ bs2,
                 float* __restrict__ outX2) {
    const unsigned FULL = 0xffffffffu;
    int row = blockIdx.x * (blockDim.x >> 5) + (threadIdx.x >> 5);
    int f   = threadIdx.x & 31;
    if (row >= BN_) return;

    // ---- L1-norm of A row (512 floats = 128 float4, 4 per lane) ----
    const float4* A4 = (const float4*)(A + (size_t)row * N_);
    float s = 0.0f;
    #pragma unroll
    for (int k = 0; k < 4; k++) {
        float4 a = A4[f + k * 32];
        s += (a.x + a.y) + (a.z + a.w);
    }
    #pragma unroll
    for (int o = 16; o; o >>= 1) s += __shfl_xor_sync(FULL, s, o);
    if (f == 0) g_inv[row] = 1.0f / fmaxf(s, 1e-12f);

    float xv = x[row * F_ + f];

    // ---- n_func -> g_x1 ----
    float h = bn1[f];
    #pragma unroll
    for (int k = 0; k < F_; k++)
        h = fmaf(__shfl_sync(FULL, xv, k), Wn1[k * F_ + f], h);
    h = fmaxf(h, 0.0f);
    float o1 = bn2[f];
    #pragma unroll
    for (int k = 0; k < F_; k++)
        o1 = fmaf(__shfl_sync(FULL, h, k), Wn2[k * F_ + f], o1);
    g_x1[row * F_ + f] = fmaxf(o1, 0.0f);

    // ---- n_self_func -> outX2 (base value; agg atomically adds) ----
    float hs = bs1[f];
    #pragma unroll
    for (int k = 0; k < F_; k++)
        hs = fmaf(__shfl_sync(FULL, xv, k), Ws1[k * F_ + f], hs);
    hs = fmaxf(hs, 0.0f);
    float o2 = bs2[f];
    #pragma unroll
    for (int k = 0; k < F_; k++)
        o2 = fmaf(__shfl_sync(FULL, hs, k), Ws2[k * F_ + f], o2);
    outX2[row * F_ + f] = fmaxf(o2, 0.0f);
}

// ---------------------------------------------------------------------------
// Aggregation + W copy: barrier-free, SMEM-free streaming.
// One warp = one (bi, chunk) tile, chunk = 128 consecutive j's (16 KB of W).
// Lane map per iteration: jo = lane>>3 (4 j's), fq = lane&7 (feature quad)
//   -> one contiguous 512 B float4 load/store per warp per iteration.
// Partial sum reduced across jo lanes, scaled by g_inv[bi], atomicAdd'ed
// into outX2 (max 4 writers per element, L2-resident 512 KB target).
// __launch_bounds__(256, 6): cap regs at 42 -> 6 blocks/SM (75% occ) to feed
// the HBM pipe; loop live state is small so no meaningful spill expected.
// ---------------------------------------------------------------------------
__global__ __launch_bounds__(256, 6)
void agg_kernel(const float* __restrict__ A, const float* __restrict__ W,
                float* __restrict__ outW, float* __restrict__ outX2) {
    const unsigned FULL = 0xffffffffu;
    int gw   = blockIdx.x * (blockDim.x >> 5) + (threadIdx.x >> 5); // 0..16383
    int lane = threadIdx.x & 31;
    int bi   = gw >> 2;           // row  (b*N + i)
    int c    = gw & 3;            // 128-j chunk within the row
    int b    = bi >> 9;           // N_ = 512
    int fq   = lane & 7;
    int jo   = lane >> 3;

    const float4* Wp   = (const float4*)(W    + (size_t)bi * N_ * F_) + c * (128 * 8);
    float4*       Op   = (float4*)      (outW + (size_t)bi * N_ * F_) + c * (128 * 8);
    const float4* x1p  = (const float4*)(g_x1 + (size_t)b  * N_ * F_) + c * (128 * 8);
    const float*  Arow = A + (size_t)bi * N_ + c * 128;

    float4 acc = make_float4(0.0f, 0.0f, 0.0f, 0.0f);

    #pragma unroll 4
    for (int jb = 0; jb < 128; jb += 4) {
        int idx  = jb * 8 + lane;             // contiguous 512B per warp
        float4 w = __ldcs(Wp + idx);          // streaming read (no reuse)
        __stcs(Op + idx, w);                  // streaming copy-out
        float  a  = __ldg(Arow + jb + jo);    // 8-lane broadcast, L1/L2 hot
        float4 xv = x1p[(jb + jo) * 8 + fq];  // x1 row, L1/L2 resident
        acc.x = fmaf(a * w.x, xv.x, acc.x);
        acc.y = fmaf(a * w.y, xv.y, acc.y);
        acc.z = fmaf(a * w.z, xv.z, acc.z);
        acc.w = fmaf(a * w.w, xv.w, acc.w);
    }

    // reduce across the 4 lanes sharing a feature-quad (xor 8, 16)
    #pragma unroll
    for (int o = 8; o <= 16; o <<= 1) {
        acc.x += __shfl_xor_sync(FULL, acc.x, o);
        acc.y += __shfl_xor_sync(FULL, acc.y, o);
        acc.z += __shfl_xor_sync(FULL, acc.z, o);
        acc.w += __shfl_xor_sync(FULL, acc.w, o);
    }

    if (lane < 8) {
        float inv  = g_inv[bi];
        float* dst = outX2 + (size_t)bi * F_ + lane * 4;
        atomicAdd(dst + 0, acc.x * inv);
        atomicAdd(dst + 1, acc.y * inv);
        atomicAdd(dst + 2, acc.z * inv);
        atomicAdd(dst + 3, acc.w * inv);
    }
}

// ---------------------------------------------------------------------------
// Launch. Inputs (metadata order): A, W, x, Wn1, bn1, Wn2, bn2, Ws1, bs1,
// Ws2, bs2. Output: [W (B*N*N*F) | x2 (B*N*F)] as float32.
// ---------------------------------------------------------------------------
extern "C" void kernel_launch(void* const* d_in, const int* in_sizes, int n_in,
                              void* d_out, int out_size) {
    const float* A   = (const float*)d_in[0];
    const float* W   = (const float*)d_in[1];
    const float* x   = (const float*)d_in[2];
    const float* Wn1 = (const float*)d_in[3];
    const float* bn1 = (const float*)d_in[4];
    const float* Wn2 = (const float*)d_in[5];
    const float* bn2 = (const float*)d_in[6];
    const float* Ws1 = (const float*)d_in[7];
    const float* bs1 = (const float*)d_in[8];
    const float* Ws2 = (const float*)d_in[9];
    const float* bs2 = (const float*)d_in[10];

    float* out   = (float*)d_out;
    float* outW  = out;
    float* outX2 = out + (size_t)B_ * N_ * N_ * F_;

    // 8 warps (rows) per block
    prep_kernel<<<BN_ / 8, 256>>>(x, A, Wn1, bn1, Wn2, bn2,
                                  Ws1, bs1, Ws2, bs2, outX2);
    // 16K independent warp-tiles: 4 chunks per row, 8 warps per block
    agg_kernel<<<(BN_ * 4) / 8, 256>>>(A, W, outW, outX2);
}

// round 7
// speedup vs baseline: 1.1818x; 1.1818x over previous
#include <cuda_runtime.h>
#include <cstdint>

#define B_  8
#define N_  512
#define F_  32
#define BN_ (B_ * N_)

#define STAGE_J     64                       // j's per pipeline stage
#define STAGE_BYTES (STAGE_J * F_ * 4)       // 8192 B
#define NBUF        4                        // SMEM ring buffers
#define NSTAGES     (N_ / STAGE_J)           // 8 stages per row

// Scratch (allocation-free rule: __device__ globals)
__device__ float g_x1[BN_ * F_];
__device__ float g_inv[BN_];

__device__ __forceinline__ uint32_t smem_u32(const void* p) {
    return (uint32_t)__cvta_generic_to_shared(p);
}

// ---------------------------------------------------------------------------
// Prep kernel: one warp per (b,n) row.
//  - g_inv[row] = 1 / max(sum_j A[row,j], eps)   (A is 0/1 -> |A| == A)
//  - g_x1 = relu(relu(x@Wn1+bn1)@Wn2+bn2)
//  - outX2 = relu(relu(x@Ws1+bs1)@Ws2+bs2)       (self path; agg adds onto it)
// ---------------------------------------------------------------------------
__global__ __launch_bounds__(256)
void prep_kernel(const float* __restrict__ x, const float* __restrict__ A,
                 const float* __restrict__ Wn1, const float* __restrict__ bn1,
                 const float* __restrict__ Wn2, const float* __restrict__ bn2,
                 const float* __restrict__ Ws1, const float* __restrict__ bs1,
                 const float* __restrict__ Ws2, const float* __restrict__ bs2,
                 float* __restrict__ outX2) {
    const unsigned FULL = 0xffffffffu;
    int row = blockIdx.x * (blockDim.x >> 5) + (threadIdx.x >> 5);
    int f   = threadIdx.x & 31;
    if (row >= BN_) return;

    const float4* A4 = (const float4*)(A + (size_t)row * N_);
    float s = 0.0f;
    #pragma unroll
    for (int k = 0; k < 4; k++) {
        float4 a = A4[f + k * 32];
        s += (a.x + a.y) + (a.z + a.w);
    }
    #pragma unroll
    for (int o = 16; o; o >>= 1) s += __shfl_xor_sync(FULL, s, o);
    if (f == 0) g_inv[row] = 1.0f / fmaxf(s, 1e-12f);

    float xv = x[row * F_ + f];

    float h = bn1[f];
    #pragma unroll
    for (int k = 0; k < F_; k++)
        h = fmaf(__shfl_sync(FULL, xv, k), Wn1[k * F_ + f], h);
    h = fmaxf(h, 0.0f);
    float o1 = bn2[f];
    #pragma unroll
    for (int k = 0; k < F_; k++)
        o1 = fmaf(__shfl_sync(FULL, h, k), Wn2[k * F_ + f], o1);
    g_x1[row * F_ + f] = fmaxf(o1, 0.0f);

    float hs = bs1[f];
    #pragma unroll
    for (int k = 0; k < F_; k++)
        hs = fmaf(__shfl_sync(FULL, xv, k), Ws1[k * F_ + f], hs);
    hs = fmaxf(hs, 0.0f);
    float o2 = bs2[f];
    #pragma unroll
    for (int k = 0; k < F_; k++)
        o2 = fmaf(__shfl_sync(FULL, hs, k), Ws2[k * F_ + f], o2);
    outX2[row * F_ + f] = fmaxf(o2, 0.0f);
}

// ---------------------------------------------------------------------------
// Aggregation + W copy via bulk-async pipeline. One block = one row (bi).
//  fill:  cp.async.bulk G->S (8KB stage of W), mbarrier complete_tx
//  copy:  cp.async.bulk S->G bulk_group (W copy-out) -- no STG.128 on LSU
//  math:  LDS.128 of W (conflict-free), LDG.128 x1 (L2-hot), LDG.32 A
//  ring:  4 buffers, fills 2 stages ahead, reuse guarded by wait_group.read 2
//  x2:    full row reduced in-block -> single plain store (no atomics)
// ---------------------------------------------------------------------------
__global__ __launch_bounds__(256)
void agg_kernel(const float* __restrict__ A, const float* __restrict__ W,
                float* __restrict__ outW, float* __restrict__ outX2) {
    __shared__ __align__(128) float sbuf[NBUF][STAGE_J * F_];   // 32 KB
    __shared__ __align__(8) unsigned long long mbar[NBUF];
    __shared__ float sacc[8][F_];

    const unsigned FULL = 0xffffffffu;
    int bi   = blockIdx.x;            // row (b*N + i)
    int b    = bi >> 9;               // N_ = 512
    int tid  = threadIdx.x;
    int warp = tid >> 5;
    int lane = tid & 31;
    int fq   = lane & 7;
    int jo   = lane >> 3;

    const char* Wrow = (const char*)(W    + (size_t)bi * N_ * F_);
    char*       Orow = (char*)      (outW + (size_t)bi * N_ * F_);
    const float4* x1p  = (const float4*)(g_x1 + (size_t)b * N_ * F_);
    const float*  Arow = A + (size_t)bi * N_;

    uint32_t sbuf_s = smem_u32(&sbuf[0][0]);
    uint32_t mbar_s = smem_u32(&mbar[0]);

    // init barriers (one thread), then make visible
    if (tid == 0) {
        #pragma unroll
        for (int i = 0; i < NBUF; i++)
            asm volatile("mbarrier.init.shared::cta.b64 [%0], 1;"
                         :: "r"(mbar_s + i * 8) : "memory");
    }
    __syncthreads();

    // prologue: fill stages 0 and 1
    if (tid == 0) {
        #pragma unroll
        for (int s = 0; s < 2; s++) {
            uint32_t mb = mbar_s + s * 8;
            asm volatile("mbarrier.arrive.expect_tx.shared::cta.b64 _, [%0], %1;"
                         :: "r"(mb), "r"((uint32_t)STAGE_BYTES) : "memory");
            asm volatile(
                "cp.async.bulk.shared::cluster.global.mbarrier::complete_tx::bytes"
                " [%0], [%1], %2, [%3];"
                :: "r"(sbuf_s + s * STAGE_BYTES),
                   "l"(Wrow + (size_t)s * STAGE_BYTES),
                   "r"((uint32_t)STAGE_BYTES), "r"(mb) : "memory");
        }
    }

    float4 acc = make_float4(0.0f, 0.0f, 0.0f, 0.0f);

    for (int s = 0; s < NSTAGES; s++) {
        int p = s & (NBUF - 1);
        uint32_t mb  = mbar_s + p * 8;
        uint32_t phs = (uint32_t)((s >> 2) & 1);

        // consumer wait (acquire)
        {
            uint32_t done;
            asm volatile(
                "{ .reg .pred q;\n\t"
                "mbarrier.try_wait.parity.acquire.cta.shared::cta.b64 q, [%1], %2;\n\t"
                "selp.b32 %0, 1, 0, q; }"
                : "=r"(done) : "r"(mb), "r"(phs) : "memory");
            if (!done) {
                asm volatile(
                    "{ .reg .pred q;\n\t"
                    "WL_%=:\n\t"
                    "mbarrier.try_wait.parity.acquire.cta.shared::cta.b64 q, [%0], %1, 0x989680;\n\t"
                    "@q bra.uni WD_%=;\n\t"
                    "bra.uni WL_%=;\n\t"
                    "WD_%=: }"
                    :: "r"(mb), "r"(phs) : "memory");
            }
        }

        // compute: warp handles 8 j's of this 64-j stage (2 iters of 4 j)
        uint32_t buf = sbuf_s + p * STAGE_BYTES;
        #pragma unroll
        for (int k = 0; k < 2; k++) {
            uint32_t a0_, a1_, a2_, a3_;
            asm volatile("ld.shared.v4.b32 {%0,%1,%2,%3}, [%4];"
                         : "=r"(a0_), "=r"(a1_), "=r"(a2_), "=r"(a3_)
                         : "r"(buf + warp * 1024 + k * 512 + lane * 16));
            float4 w4;
            w4.x = __uint_as_float(a0_); w4.y = __uint_as_float(a1_);
            w4.z = __uint_as_float(a2_); w4.w = __uint_as_float(a3_);
            int j = s * STAGE_J + warp * 8 + k * 4 + jo;
            float  a  = __ldg(Arow + j);
            float4 xv = x1p[j * 8 + fq];          // fully coalesced 512B/warp
            acc.x = fmaf(a * w4.x, xv.x, acc.x);
            acc.y = fmaf(a * w4.y, xv.y, acc.y);
            acc.z = fmaf(a * w4.z, xv.z, acc.z);
            acc.w = fmaf(a * w4.w, xv.w, acc.w);
        }

        __syncthreads();   // all warps done reading buf p

        if (tid == 0) {
            // copy-out this stage (reads SMEM asynchronously)
            asm volatile("cp.async.bulk.global.shared::cta.bulk_group [%0], [%1], %2;"
                         :: "l"(Orow + (size_t)s * STAGE_BYTES),
                            "r"(buf), "r"((uint32_t)STAGE_BYTES) : "memory");
            asm volatile("cp.async.bulk.commit_group;" ::: "memory");

            int s2 = s + 2;
            if (s2 < NSTAGES) {
                // buffer for s2 was stored at stage s2-NBUF+2 = s-2; drain its reads
                asm volatile("cp.async.bulk.wait_group.read 2;" ::: "memory");
                int p2 = s2 & (NBUF - 1);
                uint32_t mb2 = mbar_s + p2 * 8;
                asm volatile("mbarrier.arrive.expect_tx.shared::cta.b64 _, [%0], %1;"
                             :: "r"(mb2), "r"((uint32_t)STAGE_BYTES) : "memory");
                asm volatile(
                    "cp.async.bulk.shared::cluster.global.mbarrier::complete_tx::bytes"
                    " [%0], [%1], %2, [%3];"
                    :: "r"(sbuf_s + p2 * STAGE_BYTES),
                       "l"(Wrow + (size_t)s2 * STAGE_BYTES),
                       "r"((uint32_t)STAGE_BYTES), "r"(mb2) : "memory");
            }
        }
    }

    // reduce across the 4 lanes sharing a feature-quad (xor 8, 16)
    #pragma unroll
    for (int o = 8; o <= 16; o <<= 1) {
        acc.x += __shfl_xor_sync(FULL, acc.x, o);
        acc.y += __shfl_xor_sync(FULL, acc.y, o);
        acc.z += __shfl_xor_sync(FULL, acc.z, o);
        acc.w += __shfl_xor_sync(FULL, acc.w, o);
    }
    if (lane < 8) {
        sacc[warp][lane * 4 + 0] = acc.x;
        sacc[warp][lane * 4 + 1] = acc.y;
        sacc[warp][lane * 4 + 2] = acc.z;
        sacc[warp][lane * 4 + 3] = acc.w;
    }
    __syncthreads();

    // block owns the full row: plain read-modify-write (prep stored xs here)
    if (tid < F_) {
        float ssum = 0.0f;
        #pragma unroll
        for (int w8 = 0; w8 < 8; w8++) ssum += sacc[w8][tid];
        float* dst = outX2 + (size_t)bi * F_ + tid;
        *dst = fmaf(ssum, g_inv[bi], *dst);
    }
    // bulk stores drain at kernel completion
}

// ---------------------------------------------------------------------------
// Launch. Inputs (metadata order): A, W, x, Wn1, bn1, Wn2, bn2, Ws1, bs1,
// Ws2, bs2. Output: [W (B*N*N*F) | x2 (B*N*F)] as float32.
// ---------------------------------------------------------------------------
extern "C" void kernel_launch(void* const* d_in, const int* in_sizes, int n_in,
                              void* d_out, int out_size) {
    const float* A   = (const float*)d_in[0];
    const float* W   = (const float*)d_in[1];
    const float* x   = (const float*)d_in[2];
    const float* Wn1 = (const float*)d_in[3];
    const float* bn1 = (const float*)d_in[4];
    const float* Wn2 = (const float*)d_in[5];
    const float* bn2 = (const float*)d_in[6];
    const float* Ws1 = (const float*)d_in[7];
    const float* bs1 = (const float*)d_in[8];
    const float* Ws2 = (const float*)d_in[9];
    const float* bs2 = (const float*)d_in[10];

    float* out   = (float*)d_out;
    float* outW  = out;
    float* outX2 = out + (size_t)B_ * N_ * N_ * F_;

    prep_kernel<<<BN_ / 8, 256>>>(x, A, Wn1, bn1, Wn2, bn2,
                                  Ws1, bs1, Ws2, bs2, outX2);
    agg_kernel<<<BN_, 256>>>(A, W, outW, outX2);
}